// round 5
// baseline (speedup 1.0000x reference)
#include <cuda_runtime.h>

#define NBINS 64
#define ROW_LEN 8192
#define WARPS_PER_BLOCK 8          // 8 warps = 4 rows per block (2 warps/row)
#define ROWS_PER_BLOCK (WARPS_PER_BLOCK / 2)
#define BLOCK_THREADS (WARPS_PER_BLOCK * 32)
#define HALF_ROW (ROW_LEN / 2)     // 4096 elements per warp

// u16 packing, TWO BINS per word (not two lanes):
//   word = priv[pair][b>>1][lane]; bit 16*(b&1) half holds bin b's count.
//   Word index stride over lane is 1 within a 32-word row => bank = lane:
//   every warp-wide atomicAdd is PERFECTLY conflict-free, and intra-warp
//   same-word collisions are impossible (distinct lanes => distinct words).
//   The 2 warps sharing a row may hit the same word -> atomicAdd merges.
//   Max count per half = 2 warps x 128 elems/lane = 256 << 65536 (no carry).
//   16 KB smem/block -> 8 blocks/SM -> 64 warps, whole 1024-block grid
//   resident in ONE wave (capacity 148*8 = 1184).
__global__ __launch_bounds__(BLOCK_THREADS, 8)
void hist_rows_kernel(const float* __restrict__ x, float* __restrict__ out) {
    __shared__ unsigned int priv[ROWS_PER_BLOCK][NBINS / 2][32];

    const int warp = threadIdx.x >> 5;
    const int lane = threadIdx.x & 31;
    const int pair = warp >> 1;            // which row within the block
    const int half = warp & 1;             // which half of the row
    const int row  = blockIdx.x * ROWS_PER_BLOCK + pair;

    unsigned int* slab = &priv[pair][0][0];   // (NBINS/2)*32 words

    // Zero all counters: 4 * 32 * 32 = 4096 words = 16 per thread.
    unsigned int* flat = &priv[0][0][0];
    #pragma unroll
    for (int i = 0; i < (ROWS_PER_BLOCK * (NBINS / 2) * 32) / BLOCK_THREADS; i++)
        flat[threadIdx.x + i * BLOCK_THREADS] = 0u;
    __syncthreads();

    const float4* __restrict__ xr =
        (const float4*)(x + (size_t)row * ROW_LEN + (size_t)half * HALF_ROW);

    const float scale = 64.0f / 6.0f;   // NBINS / (VMAX - VMIN), fp32-rounded like ref

    // 4096 floats = 1024 float4 per warp; 32 float4 per lane; unroll 4 for MLP.
    #pragma unroll 1
    for (int it = 0; it < (HALF_ROW / 4) / 32; it += 4) {
        float4 v0 = xr[(it + 0) * 32 + lane];
        float4 v1 = xr[(it + 1) * 32 + lane];
        float4 v2 = xr[(it + 2) * 32 + lane];
        float4 v3 = xr[(it + 3) * 32 + lane];

        #pragma unroll
        for (int k = 0; k < 4; k++) {
            float4 v = (k == 0) ? v0 : (k == 1) ? v1 : (k == 2) ? v2 : v3;
            float f[4] = {v.x, v.y, v.z, v.w};
            #pragma unroll
            for (int j = 0; j < 4; j++) {
                // Exactly the reference fp32 sequence: (x - VMIN) then * scale,
                // floor (round toward -inf), clamp to [0, 63].
                int b = __float2int_rd(__fmul_rn(__fadd_rn(f[j], 3.0f), scale));
                b = max(0, min(NBINS - 1, b));
                unsigned int incr = 1u << ((b & 1) << 4);
                atomicAdd(&slab[(b >> 1) * 32 + lane], incr);  // bank = lane
            }
        }
    }

    __syncthreads();

    // Reduce: warp0 of the pair handles bins [0,32), warp1 bins [32,64).
    // Lane sums 32 lane-columns of its bin's half-word. Rotated column index
    // (t+lane)&31 keeps banks distinct per lane on every step.
    const int bin = half * 32 + lane;
    const int shift = (bin & 1) << 4;
    unsigned int s = 0;
    #pragma unroll
    for (int t = 0; t < 32; t++) {
        unsigned int v = slab[(bin >> 1) * 32 + ((t + lane) & 31)];
        s += (v >> shift) & 0xFFFFu;
    }

    const float inv_n = 1.0f / (float)ROW_LEN;
    out[(size_t)row * NBINS + bin] = (float)s * inv_n;
}

extern "C" void kernel_launch(void* const* d_in, const int* in_sizes, int n_in,
                              void* d_out, int out_size) {
    const float* x = (const float*)d_in[0];
    float* out = (float*)d_out;

    int nrows = in_sizes[0] / ROW_LEN;             // 4096
    int grid = nrows / ROWS_PER_BLOCK;             // 1024 blocks, single wave

    hist_rows_kernel<<<grid, BLOCK_THREADS>>>(x, out);
}

// round 6
// speedup vs baseline: 1.0631x; 1.0631x over previous
#include <cuda_runtime.h>

#define NBINS 64
#define ROW_LEN 8192
#define WARPS_PER_BLOCK 8          // 8 warps = 4 rows per block (2 warps/row)
#define ROWS_PER_BLOCK (WARPS_PER_BLOCK / 2)
#define BLOCK_THREADS (WARPS_PER_BLOCK * 32)
#define HALF_ROW (ROW_LEN / 2)     // 4096 elements per warp

// u16-packed lane-pair histograms (as in R3) + XOR-8 sub-index remap:
//   sub  = (lane & 15) ^ (lane >= 16 ? 8 : 0)        (computed ONCE)
//   word = priv[pair][bin*16 + sub]; lane<16 low half, lane>=16 high half.
//   incr = 1 or 1<<16, constant per lane.
//   Bank check: low lane bank = (16*(b0&1) + s) % 32,
//               high lane bank = (16*(b1&1) + (s^8)) % 32.
//   Equal  <=>  16*(p0-p1) == +-8 (mod 32)  -> impossible for ANY bin pair:
//   every warp-wide atomicAdd is fully conflict-free with ZERO per-element
//   instruction overhead. Same-word intra-warp collision needs s == s^8:
//   impossible. Cross-warp (the 2 warps sharing a row) same-word hits are
//   merged by the atomic. Max count per half = 2*128 = 256 << 65536.
//   16 KB smem/block -> 8 blocks/SM -> 64 warps; whole 1024-block grid
//   resident in ONE wave (capacity 148*8 = 1184).
__global__ __launch_bounds__(BLOCK_THREADS, 8)
void hist_rows_kernel(const float* __restrict__ x, float* __restrict__ out) {
    __shared__ unsigned int priv[ROWS_PER_BLOCK][NBINS][16];

    const int warp = threadIdx.x >> 5;
    const int lane = threadIdx.x & 31;
    const int pair = warp >> 1;            // which row within the block
    const int half = warp & 1;             // which half of the row
    const int row  = blockIdx.x * ROWS_PER_BLOCK + pair;
    const int sub  = (lane & 15) ^ ((lane >> 1) & 8);   // XOR 8 for lanes >= 16
    const unsigned int incr = (lane & 16) ? 0x10000u : 1u;

    unsigned int* slab = &priv[pair][0][0];   // NBINS*16 words

    // Zero all counters (4096 words / 256 threads = 16 each).
    unsigned int* flat = &priv[0][0][0];
    #pragma unroll
    for (int i = 0; i < (ROWS_PER_BLOCK * NBINS * 16) / BLOCK_THREADS; i++)
        flat[threadIdx.x + i * BLOCK_THREADS] = 0u;
    __syncthreads();

    const float4* __restrict__ xr =
        (const float4*)(x + (size_t)row * ROW_LEN + (size_t)half * HALF_ROW);

    const float scale = 64.0f / 6.0f;   // NBINS / (VMAX - VMIN), fp32-rounded like ref

    // 4096 floats = 1024 float4 per warp; 32 float4 per lane; unroll 4 for MLP.
    #pragma unroll 1
    for (int it = 0; it < (HALF_ROW / 4) / 32; it += 4) {
        float4 v0 = xr[(it + 0) * 32 + lane];
        float4 v1 = xr[(it + 1) * 32 + lane];
        float4 v2 = xr[(it + 2) * 32 + lane];
        float4 v3 = xr[(it + 3) * 32 + lane];

        #pragma unroll
        for (int k = 0; k < 4; k++) {
            float4 v = (k == 0) ? v0 : (k == 1) ? v1 : (k == 2) ? v2 : v3;
            float f[4] = {v.x, v.y, v.z, v.w};
            #pragma unroll
            for (int j = 0; j < 4; j++) {
                // Exactly the reference fp32 sequence: (x - VMIN) then * scale,
                // floor (round toward -inf), clamp to [0, 63].
                int b = __float2int_rd(__fmul_rn(__fadd_rn(f[j], 3.0f), scale));
                b = max(0, min(NBINS - 1, b));
                atomicAdd(&slab[b * 16 + sub], incr);   // provably conflict-free
            }
        }
    }

    __syncthreads();

    // Reduce: warp0 of the pair handles bins [0,32), warp1 bins [32,64).
    // Sum all 16 packed words per bin (column permutation is sum-invariant).
    const int bin = half * 32 + lane;
    unsigned int s = 0;
    #pragma unroll
    for (int t = 0; t < 16; t++) {
        unsigned int v = slab[bin * 16 + ((t + lane) & 15)];
        s += (v & 0xFFFFu) + (v >> 16);
    }

    const float inv_n = 1.0f / (float)ROW_LEN;
    out[(size_t)row * NBINS + bin] = (float)s * inv_n;
}

extern "C" void kernel_launch(void* const* d_in, const int* in_sizes, int n_in,
                              void* d_out, int out_size) {
    const float* x = (const float*)d_in[0];
    float* out = (float*)d_out;

    int nrows = in_sizes[0] / ROW_LEN;             // 4096
    int grid = nrows / ROWS_PER_BLOCK;             // 1024 blocks, single wave

    hist_rows_kernel<<<grid, BLOCK_THREADS>>>(x, out);
}

// round 7
// speedup vs baseline: 1.0643x; 1.0012x over previous
#include <cuda_runtime.h>

#define NBINS 64
#define ROW_LEN 8192
#define WARPS_PER_BLOCK 8          // 8 warps = 4 rows per block (2 warps/row)
#define ROWS_PER_BLOCK 4
#define BLOCK_THREADS (WARPS_PER_BLOCK * 32)
#define HALF_ROW (ROW_LEN / 2)     // 4096 elements per warp

// u16 packing along the ROW axis with full 32-column banking:
//   slab[g][bin][lane] (u32): low half counts row 2g, high half row 2g+1.
//   word index stride over lane = 1 => bank = lane: EVERY warp-wide
//   atomicAdd is exactly 1 wavefront, zero conflicts, and the increment
//   (1 or 1<<16) is a per-warp constant -> zero per-element ALU overhead.
//   Intra-warp same-word collisions impossible (distinct lanes). The 4
//   warps sharing a slab may hit the same word cross-warp -> atomicAdd
//   merges; max count per half = 2 warps x 128 elems/lane = 256 << 65536,
//   so halves can never carry into each other.
//   smem = 2 slabs x 8 KB = 16 KB/block -> 8 blocks/SM -> 64 warps, and the
//   whole 1024-block grid is resident in ONE wave (capacity 148*8 = 1184).
__global__ __launch_bounds__(BLOCK_THREADS, 8)
void hist_rows_kernel(const float* __restrict__ x, float* __restrict__ out) {
    __shared__ unsigned int priv[2][NBINS][32];

    const int warp   = threadIdx.x >> 5;
    const int lane   = threadIdx.x & 31;
    const int g      = warp >> 2;          // which slab (2 per block)
    const int rowsel = (warp >> 1) & 1;    // which row of the slab's pair
    const int half   = warp & 1;           // which half of that row
    const int row    = blockIdx.x * ROWS_PER_BLOCK + g * 2 + rowsel;
    const unsigned int incr = rowsel ? 0x10000u : 1u;

    unsigned int* slab = &priv[g][0][0];   // NBINS*32 words

    // Zero all counters (2*64*32 = 4096 words / 256 threads = 16 each).
    unsigned int* flat = &priv[0][0][0];
    #pragma unroll
    for (int i = 0; i < (2 * NBINS * 32) / BLOCK_THREADS; i++)
        flat[threadIdx.x + i * BLOCK_THREADS] = 0u;
    __syncthreads();

    const float4* __restrict__ xr =
        (const float4*)(x + (size_t)row * ROW_LEN + (size_t)half * HALF_ROW);

    const float scale = 64.0f / 6.0f;   // NBINS / (VMAX - VMIN), fp32-rounded like ref

    // 4096 floats = 1024 float4 per warp; 32 float4 per lane; unroll 4 for MLP.
    #pragma unroll 1
    for (int it = 0; it < (HALF_ROW / 4) / 32; it += 4) {
        float4 v0 = xr[(it + 0) * 32 + lane];
        float4 v1 = xr[(it + 1) * 32 + lane];
        float4 v2 = xr[(it + 2) * 32 + lane];
        float4 v3 = xr[(it + 3) * 32 + lane];

        #pragma unroll
        for (int k = 0; k < 4; k++) {
            float4 v = (k == 0) ? v0 : (k == 1) ? v1 : (k == 2) ? v2 : v3;
            float f[4] = {v.x, v.y, v.z, v.w};
            #pragma unroll
            for (int j = 0; j < 4; j++) {
                // Exactly the reference fp32 sequence: (x - VMIN) then * scale,
                // floor (round toward -inf), clamp to [0, 63].
                int b = __float2int_rd(__fmul_rn(__fadd_rn(f[j], 3.0f), scale));
                b = max(0, min(NBINS - 1, b));
                atomicAdd(&slab[b * 32 + lane], incr);   // bank = lane, 1 wavefront
            }
        }
    }

    __syncthreads();

    // Reduce: each warp outputs 32 bins of ITS OWN row (warp half=0 -> bins
    // [0,32), half=1 -> bins [32,64)), extracting its row's u16 half.
    // Rotated column (t+lane)&31 keeps banks distinct per lane every step.
    const int bin = half * 32 + lane;
    const int shift = rowsel << 4;
    unsigned int s = 0;
    #pragma unroll
    for (int t = 0; t < 32; t++) {
        s += (slab[bin * 32 + ((t + lane) & 31)] >> shift) & 0xFFFFu;
    }

    const float inv_n = 1.0f / (float)ROW_LEN;
    out[(size_t)row * NBINS + bin] = (float)s * inv_n;
}

extern "C" void kernel_launch(void* const* d_in, const int* in_sizes, int n_in,
                              void* d_out, int out_size) {
    const float* x = (const float*)d_in[0];
    float* out = (float*)d_out;

    int nrows = in_sizes[0] / ROW_LEN;             // 4096
    int grid = nrows / ROWS_PER_BLOCK;             // 1024 blocks, single wave

    hist_rows_kernel<<<grid, BLOCK_THREADS>>>(x, out);
}

// round 8
// speedup vs baseline: 1.0731x; 1.0083x over previous
#include <cuda_runtime.h>

#define NBINS 64
#define ROW_LEN 8192
#define WARPS_PER_BLOCK 8          // 8 warps = 4 rows per block (2 warps/row)
#define ROWS_PER_BLOCK 4
#define BLOCK_THREADS (WARPS_PER_BLOCK * 32)
#define HALF_ROW (ROW_LEN / 2)     // 4096 elements per warp
#define VECS (HALF_ROW / 4 / 32)   // 32 float4 per lane

// Layout identical to R7 (u16 row-packing, bank = lane, conflict-free,
// per-warp-constant increment). New: software-pipelined ping-pong loads so
// each warp always has the next stage's 2 LDG.128 in flight while crunching
// the current 8 elements -> exposed DRAM latency ~eliminated.
// 16 KB smem/block, ~36 regs -> 7 blocks/SM = 56 warps; grid 1024 <= 1036
// capacity -> single wave.
__global__ __launch_bounds__(BLOCK_THREADS, 7)
void hist_rows_kernel(const float* __restrict__ x, float* __restrict__ out) {
    __shared__ unsigned int priv[2][NBINS][32];

    const int warp   = threadIdx.x >> 5;
    const int lane   = threadIdx.x & 31;
    const int g      = warp >> 2;          // which slab (2 per block)
    const int rowsel = (warp >> 1) & 1;    // which row of the slab's pair
    const int half   = warp & 1;           // which half of that row
    const int row    = blockIdx.x * ROWS_PER_BLOCK + g * 2 + rowsel;
    const unsigned int incr = rowsel ? 0x10000u : 1u;

    unsigned int* cell = &priv[g][0][0] + lane;   // bank = lane forever

    // Zero all counters (2*64*32 = 4096 words / 256 threads = 16 each).
    unsigned int* flat = &priv[0][0][0];
    #pragma unroll
    for (int i = 0; i < (2 * NBINS * 32) / BLOCK_THREADS; i++)
        flat[threadIdx.x + i * BLOCK_THREADS] = 0u;
    __syncthreads();

    const float4* __restrict__ xr =
        (const float4*)(x + (size_t)row * ROW_LEN + (size_t)half * HALF_ROW) + lane;

    const float scale = 64.0f / 6.0f;   // NBINS / (VMAX - VMIN), fp32-rounded like ref

    // Exactly the reference fp32 sequence per element: (x - VMIN), * scale,
    // floor (round toward -inf), clamp to [0, 63]. Then one conflict-free atomic.
    #define PROC4(v)                                                          \
        do {                                                                  \
            float _f[4] = {(v).x, (v).y, (v).z, (v).w};                       \
            _Pragma("unroll")                                                 \
            for (int _j = 0; _j < 4; _j++) {                                  \
                int _b = __float2int_rd(__fmul_rn(__fadd_rn(_f[_j], 3.0f), scale)); \
                _b = max(0, min(NBINS - 1, _b));                              \
                atomicAdd(&cell[_b * 32], incr);                              \
            }                                                                 \
        } while (0)

    // Ping-pong double buffer: 4 live float4 (16 regs). Loads for the next
    // 2-vector stage are issued before processing the current stage.
    float4 p0 = xr[0 * 32];
    float4 p1 = xr[1 * 32];
    float4 q0, q1;

    #pragma unroll 1
    for (int s = 0; s < (VECS - 4) / 4; s++) {      // 7 iterations, 4 vecs each
        q0 = xr[(4 * s + 2) * 32];
        q1 = xr[(4 * s + 3) * 32];
        PROC4(p0);
        PROC4(p1);
        p0 = xr[(4 * s + 4) * 32];
        p1 = xr[(4 * s + 5) * 32];
        PROC4(q0);
        PROC4(q1);
    }
    // Tail: vectors 30, 31 plus the last p pair.
    q0 = xr[(VECS - 2) * 32];
    q1 = xr[(VECS - 1) * 32];
    PROC4(p0);
    PROC4(p1);
    PROC4(q0);
    PROC4(q1);

    #undef PROC4

    __syncthreads();

    // Reduce: each warp outputs 32 bins of ITS OWN row (half=0 -> bins [0,32),
    // half=1 -> [32,64)), extracting its row's u16 half. Rotated column
    // (t+lane)&31 keeps banks distinct per lane.
    unsigned int* slab = &priv[g][0][0];
    const int bin = half * 32 + lane;
    const int shift = rowsel << 4;
    unsigned int s = 0;
    #pragma unroll
    for (int t = 0; t < 32; t++) {
        s += (slab[bin * 32 + ((t + lane) & 31)] >> shift) & 0xFFFFu;
    }

    const float inv_n = 1.0f / (float)ROW_LEN;
    out[(size_t)row * NBINS + bin] = (float)s * inv_n;
}

extern "C" void kernel_launch(void* const* d_in, const int* in_sizes, int n_in,
                              void* d_out, int out_size) {
    const float* x = (const float*)d_in[0];
    float* out = (float*)d_out;

    int nrows = in_sizes[0] / ROW_LEN;             // 4096
    int grid = nrows / ROWS_PER_BLOCK;             // 1024 blocks, single wave

    hist_rows_kernel<<<grid, BLOCK_THREADS>>>(x, out);
}